// round 9
// baseline (speedup 1.0000x reference)
#include <cuda_runtime.h>
#include <mma.h>
using namespace nvcuda;

#define NUM_HEADS 16
#define KSPLIT 4
#define TM 64
#define TN 64
#define TKT 32
#define THREADS 128
#define A_STRIDE 36     // 32 k + 4 pad
#define B_STRIDE 68     // 64 n + 4 pad
#define MAXN 2048
#define HDIM 512
#define NROUNDS (MAXN / THREADS)   // 16

__device__ float d_part[KSPLIT * MAXN * HDIM];   // 16MB fp32 partials

// ---------------------------------------------------------------------------
// Grouped GEMM, tf32 tensor cores, split-K=4, with IN-KERNEL routing.
// Each CTA scans idx (8KB, L2-hot) and rebuilds its head's token list in
// index order: one ballot per 128-token round cached in smem, one barrier,
// then rank arithmetic per thread. No bucket kernel, no atomics.
// blockIdx.z encodes head*KSPLIT + ks.
// ---------------------------------------------------------------------------
__global__ __launch_bounds__(THREADS, 4) void mlin_wmma(
    const float* __restrict__ X,     // (N, D)
    const float* __restrict__ W,     // (NUM_HEADS, D, H)
    const int*   __restrict__ idx,   // (N,) int32
    int N, int D, int H)
{
    const int head = blockIdx.z >> 2;
    const int ks   = blockIdx.z & (KSPLIT - 1);
    const int m0   = blockIdx.y * TM;
    const int h0   = blockIdx.x * TN;
    const int kbeg = ks * (D / KSPLIT);          // 128

    __shared__ __align__(16) float As[2][TM][A_STRIDE];
    __shared__ __align__(16) float Bs[2][TKT][B_STRIDE];
    __shared__ int      tok_s[TM];
    __shared__ unsigned ball[NROUNDS][4];

    const int tid  = threadIdx.x;
    const int wid  = tid >> 5;
    const int lane = tid & 31;
    const unsigned lanes_below = (1u << lane) - 1u;

    // ---- in-CTA routing: find tokens of `head` in index order ----
    int myv[NROUNDS];
    #pragma unroll
    for (int r = 0; r < NROUNDS; r++) {
        const int i = r * THREADS + tid;
        myv[r] = (i < N) ? (idx[i] & (NUM_HEADS - 1)) : -1;
    }
    if (tid < TM) tok_s[tid] = -1;
    #pragma unroll
    for (int r = 0; r < NROUNDS; r++) {
        unsigned bm = __ballot_sync(0xffffffffu, myv[r] == head);
        if (lane == 0) ball[r][wid] = bm;
    }
    __syncthreads();

    int base = 0;
    #pragma unroll
    for (int r = 0; r < NROUNDS; r++) {
        const unsigned w0 = ball[r][0], w1 = ball[r][1], w2 = ball[r][2], w3 = ball[r][3];
        if (myv[r] == head) {
            int before = 0;
            if (wid > 0) before += __popc(w0);
            if (wid > 1) before += __popc(w1);
            if (wid > 2) before += __popc(w2);
            const unsigned own = (wid == 0) ? w0 : (wid == 1) ? w1 : (wid == 2) ? w2 : w3;
            const int pos = base + before + __popc(own & lanes_below);
            const int rel = pos - m0;
            if (rel >= 0 && rel < TM) tok_s[rel] = r * THREADS + tid;
        }
        base += __popc(w0) + __popc(w1) + __popc(w2) + __popc(w3);
    }
    const int M = base;
    __syncthreads();
    if (m0 >= M) return;

    // ---- GEMM mainloop (as R7) ----
    const int a_row = tid >> 1;              // 0..63
    const int a_k0  = (tid & 1) * 16;        // 0 or 16
    const int b_row = tid >> 2;              // 0..31
    const int b_n0  = (tid & 3) * 16;        // 0,16,32,48

    const int a_tok = tok_s[a_row];
    const bool a_ok = (a_tok >= 0);
    const float* aptr = X + (size_t)(a_ok ? a_tok : 0) * D + kbeg;
    const float* wptr = W + (size_t)head * D * H + (size_t)kbeg * H + h0;

    const int wm = (wid >> 1) * 32;
    const int wn = (wid & 1) * 32;

    wmma::fragment<wmma::accumulator, 16, 16, 8, float> acc[2][2];
    #pragma unroll
    for (int i = 0; i < 2; i++)
        #pragma unroll
        for (int j = 0; j < 2; j++)
            wmma::fill_fragment(acc[i][j], 0.0f);

    float4 ar[4], br[4];

    #define CVT4(v) make_float4(wmma::__float_to_tf32((v).x), wmma::__float_to_tf32((v).y), \
                                wmma::__float_to_tf32((v).z), wmma::__float_to_tf32((v).w))

    #pragma unroll
    for (int i = 0; i < 4; i++) {
        ar[i] = a_ok ? *reinterpret_cast<const float4*>(aptr + a_k0 + i * 4)
                     : make_float4(0.f, 0.f, 0.f, 0.f);
        br[i] = *reinterpret_cast<const float4*>(wptr + (size_t)b_row * H + b_n0 + i * 4);
    }
    #pragma unroll
    for (int i = 0; i < 4; i++) {
        *reinterpret_cast<float4*>(&As[0][a_row][a_k0 + i * 4]) = CVT4(ar[i]);
        *reinterpret_cast<float4*>(&Bs[0][b_row][b_n0 + i * 4]) = CVT4(br[i]);
    }
    __syncthreads();

    const int NT = D / KSPLIT / TKT;   // 4
    #pragma unroll
    for (int t = 0; t < NT; t++) {
        const int buf = t & 1;

        if (t + 1 < NT) {
            const int kt = (t + 1) * TKT;
            #pragma unroll
            for (int i = 0; i < 4; i++) {
                ar[i] = a_ok ? *reinterpret_cast<const float4*>(aptr + kt + a_k0 + i * 4)
                             : make_float4(0.f, 0.f, 0.f, 0.f);
                br[i] = *reinterpret_cast<const float4*>(wptr + (size_t)(kt + b_row) * H + b_n0 + i * 4);
            }
        }

        #pragma unroll
        for (int kk = 0; kk < TKT; kk += 8) {
            wmma::fragment<wmma::matrix_a, 16, 16, 8, wmma::precision::tf32, wmma::row_major> af[2];
            wmma::fragment<wmma::matrix_b, 16, 16, 8, wmma::precision::tf32, wmma::row_major> bf[2];
            #pragma unroll
            for (int i = 0; i < 2; i++)
                wmma::load_matrix_sync(af[i], &As[buf][wm + i * 16][kk], A_STRIDE);
            #pragma unroll
            for (int j = 0; j < 2; j++)
                wmma::load_matrix_sync(bf[j], &Bs[buf][kk][wn + j * 16], B_STRIDE);
            #pragma unroll
            for (int i = 0; i < 2; i++)
                #pragma unroll
                for (int j = 0; j < 2; j++)
                    wmma::mma_sync(acc[i][j], af[i], bf[j], acc[i][j]);
        }

        if (t + 1 < NT) {
            const int nbuf = (t + 1) & 1;
            #pragma unroll
            for (int i = 0; i < 4; i++) {
                *reinterpret_cast<float4*>(&As[nbuf][a_row][a_k0 + i * 4]) = CVT4(ar[i]);
                *reinterpret_cast<float4*>(&Bs[nbuf][b_row][b_n0 + i * 4]) = CVT4(br[i]);
            }
        }
        __syncthreads();
    }
    #undef CVT4

    // epilogue: stage through smem (reuse As/Bs region), scatter to d_part[ks]
    float* Cs = &As[0][0][0];    // 64 x 68 staging
    #pragma unroll
    for (int i = 0; i < 2; i++)
        #pragma unroll
        for (int j = 0; j < 2; j++)
            wmma::store_matrix_sync(&Cs[(wm + i * 16) * B_STRIDE + wn + j * 16], acc[i][j],
                                    B_STRIDE, wmma::mem_row_major);
    __syncthreads();

    float* pbase = d_part + (size_t)ks * MAXN * HDIM;
    const int c_row  = tid >> 1;              // 0..63
    const int c_col0 = (tid & 1) * 32;
    if (m0 + c_row < M) {
        const int tok = tok_s[c_row];
        float* yptr = pbase + (size_t)tok * H + h0 + c_col0;
        #pragma unroll
        for (int j = 0; j < 32; j += 4)
            *reinterpret_cast<float4*>(yptr + j) =
                *reinterpret_cast<const float4*>(&Cs[c_row * B_STRIDE + c_col0 + j]);
    }
}

// ---------------------------------------------------------------------------
// Reduce partials + bias (fixed order -> deterministic).
// ---------------------------------------------------------------------------
__global__ __launch_bounds__(256) void reduce_kernel(
    const int* __restrict__ idx,
    const float* __restrict__ Bias,   // (NUM_HEADS, H)
    float* __restrict__ Y,            // (N, H)
    int H)
{
    const int i4  = blockIdx.x * 256 + threadIdx.x;       // float4 index
    const int tok = i4 / (H / 4);
    const int c4  = (i4 % (H / 4)) * 4;
    const int head = idx[tok] & (NUM_HEADS - 1);

    const size_t o = (size_t)tok * H + c4;
    float4 s  = *reinterpret_cast<const float4*>(d_part + o);
    #pragma unroll
    for (int k = 1; k < KSPLIT; k++) {
        float4 p = *reinterpret_cast<const float4*>(d_part + (size_t)k * MAXN * HDIM + o);
        s.x += p.x; s.y += p.y; s.z += p.z; s.w += p.w;
    }
    float4 b = *reinterpret_cast<const float4*>(Bias + (size_t)head * H + c4);
    s.x += b.x; s.y += b.y; s.z += b.z; s.w += b.w;
    *reinterpret_cast<float4*>(Y + o) = s;
}

extern "C" void kernel_launch(void* const* d_in, const int* in_sizes, int n_in,
                              void* d_out, int out_size) {
    const float* X    = (const float*)d_in[0];   // (N, D) fp32
    const int*   idx  = (const int*)d_in[1];     // (N,)   int32
    const float* W    = (const float*)d_in[2];   // (16, D, H) fp32
    const float* Bias = (const float*)d_in[3];   // (16, H) fp32
    float*       Y    = (float*)d_out;           // (N, H) fp32

    const int N = in_sizes[1];
    const int D = in_sizes[0] / N;
    const int H = in_sizes[3] / NUM_HEADS;

    // grid.y = 4 m-tiles covers buckets up to 256 tokens (11.6 sigma at N=2048)
    dim3 grid(H / TN, 4, NUM_HEADS * KSPLIT);
    mlin_wmma<<<grid, THREADS>>>(X, W, idx, N, D, H);

    const int total4 = N * H / 4;
    reduce_kernel<<<total4 / 256, 256>>>(idx, Bias, Y, H);
}

// round 11
// speedup vs baseline: 1.1718x; 1.1718x over previous
#include <cuda_runtime.h>
#include <mma.h>
using namespace nvcuda;

#define NUM_HEADS 16
#define KSPLIT 4
#define TM 64
#define TN 64
#define TKT 32
#define THREADS 128
#define A_STRIDE 36     // 32 k + 4 pad
#define B_STRIDE 68     // 64 n + 4 pad
#define MAXN 2048
#define HDIM 512
#define MAXB 256        // per-head bucket capacity (mean 128, sigma~11 -> safe)

__device__ int d_order[NUM_HEADS * MAXB];
__device__ int d_cnt[NUM_HEADS];
__device__ float d_part[KSPLIT * MAXN * HDIM];   // 16MB fp32 partials

// ---------------------------------------------------------------------------
// Kernel 1: bucket, one CTA per head (16 CTAs, fully parallel, no atomics,
// no cross-head prefix). Each CTA compacts its head's tokens in index order
// into d_order[head*MAXB + .] via ballot ranks.
// ---------------------------------------------------------------------------
__global__ __launch_bounds__(256) void bucket16(const int* __restrict__ idx, int N) {
    const int head = blockIdx.x;
    __shared__ unsigned ball[8][8];            // [round][warp]
    const int tid = threadIdx.x;
    const int w = tid >> 5;
    const int l = tid & 31;
    const unsigned below = (1u << l) - 1u;

    int my[8];
    #pragma unroll
    for (int r = 0; r < 8; r++) {
        const int i = r * 256 + tid;
        my[r] = (i < N) ? (idx[i] & (NUM_HEADS - 1)) : -1;
    }
    #pragma unroll
    for (int r = 0; r < 8; r++) {
        unsigned bm = __ballot_sync(0xffffffffu, my[r] == head);
        if (l == 0) ball[r][w] = bm;
    }
    __syncthreads();

    int base = 0;
    #pragma unroll
    for (int r = 0; r < 8; r++) {
        int before = 0, tot = 0;
        unsigned own = 0;
        #pragma unroll
        for (int ww = 0; ww < 8; ww++) {
            const unsigned b = ball[r][ww];
            if (ww < w) before += __popc(b);
            if (ww == w) own = b;
            tot += __popc(b);
        }
        if (my[r] == head) {
            const int pos = base + before + __popc(own & below);
            if (pos < MAXB) d_order[head * MAXB + pos] = r * 256 + tid;
        }
        base += tot;
    }
    if (tid == 0) d_cnt[head] = (base < MAXB) ? base : MAXB;
}

// ---------------------------------------------------------------------------
// Kernel 2: grouped GEMM, tf32 tensor cores, split-K=4 (as R7).
// blockIdx.z encodes head*KSPLIT + ks.
// ---------------------------------------------------------------------------
__global__ __launch_bounds__(THREADS, 4) void mlin_wmma(
    const float* __restrict__ X,     // (N, D)
    const float* __restrict__ W,     // (NUM_HEADS, D, H)
    int D, int H)
{
    const int head = blockIdx.z >> 2;
    const int ks   = blockIdx.z & (KSPLIT - 1);
    const int M    = d_cnt[head];
    const int m0   = blockIdx.y * TM;
    if (m0 >= M) return;
    const int h0   = blockIdx.x * TN;
    const int kbeg = ks * (D / KSPLIT);          // 128

    __shared__ __align__(16) float As[2][TM][A_STRIDE];
    __shared__ __align__(16) float Bs[2][TKT][B_STRIDE];
    __shared__ int tok_s[TM];

    const int tid = threadIdx.x;
    const int wid = tid >> 5;

    if (tid < TM) {
        int m = m0 + tid;
        tok_s[tid] = (m < M) ? d_order[head * MAXB + m] : -1;
    }
    __syncthreads();

    const int a_row = tid >> 1;              // 0..63
    const int a_k0  = (tid & 1) * 16;        // 0 or 16
    const int b_row = tid >> 2;              // 0..31
    const int b_n0  = (tid & 3) * 16;        // 0,16,32,48

    const int a_tok = tok_s[a_row];
    const bool a_ok = (a_tok >= 0);
    const float* aptr = X + (size_t)(a_ok ? a_tok : 0) * D + kbeg;
    const float* wptr = W + (size_t)head * D * H + (size_t)kbeg * H + h0;

    const int wm = (wid >> 1) * 32;
    const int wn = (wid & 1) * 32;

    wmma::fragment<wmma::accumulator, 16, 16, 8, float> acc[2][2];
    #pragma unroll
    for (int i = 0; i < 2; i++)
        #pragma unroll
        for (int j = 0; j < 2; j++)
            wmma::fill_fragment(acc[i][j], 0.0f);

    float4 ar[4], br[4];

    #define CVT4(v) make_float4(wmma::__float_to_tf32((v).x), wmma::__float_to_tf32((v).y), \
                                wmma::__float_to_tf32((v).z), wmma::__float_to_tf32((v).w))

    #pragma unroll
    for (int i = 0; i < 4; i++) {
        ar[i] = a_ok ? *reinterpret_cast<const float4*>(aptr + a_k0 + i * 4)
                     : make_float4(0.f, 0.f, 0.f, 0.f);
        br[i] = *reinterpret_cast<const float4*>(wptr + (size_t)b_row * H + b_n0 + i * 4);
    }
    #pragma unroll
    for (int i = 0; i < 4; i++) {
        *reinterpret_cast<float4*>(&As[0][a_row][a_k0 + i * 4]) = CVT4(ar[i]);
        *reinterpret_cast<float4*>(&Bs[0][b_row][b_n0 + i * 4]) = CVT4(br[i]);
    }
    __syncthreads();

    const int NT = D / KSPLIT / TKT;   // 4
    #pragma unroll
    for (int t = 0; t < NT; t++) {
        const int buf = t & 1;

        if (t + 1 < NT) {
            const int kt = (t + 1) * TKT;
            #pragma unroll
            for (int i = 0; i < 4; i++) {
                ar[i] = a_ok ? *reinterpret_cast<const float4*>(aptr + kt + a_k0 + i * 4)
                             : make_float4(0.f, 0.f, 0.f, 0.f);
                br[i] = *reinterpret_cast<const float4*>(wptr + (size_t)(kt + b_row) * H + b_n0 + i * 4);
            }
        }

        #pragma unroll
        for (int kk = 0; kk < TKT; kk += 8) {
            wmma::fragment<wmma::matrix_a, 16, 16, 8, wmma::precision::tf32, wmma::row_major> af[2];
            wmma::fragment<wmma::matrix_b, 16, 16, 8, wmma::precision::tf32, wmma::row_major> bf[2];
            #pragma unroll
            for (int i = 0; i < 2; i++)
                wmma::load_matrix_sync(af[i], &As[buf][wm + i * 16][kk], A_STRIDE);
            #pragma unroll
            for (int j = 0; j < 2; j++)
                wmma::load_matrix_sync(bf[j], &Bs[buf][kk][wn + j * 16], B_STRIDE);
            #pragma unroll
            for (int i = 0; i < 2; i++)
                #pragma unroll
                for (int j = 0; j < 2; j++)
                    wmma::mma_sync(acc[i][j], af[i], bf[j], acc[i][j]);
        }

        if (t + 1 < NT) {
            const int nbuf = (t + 1) & 1;
            #pragma unroll
            for (int i = 0; i < 4; i++) {
                *reinterpret_cast<float4*>(&As[nbuf][a_row][a_k0 + i * 4]) = CVT4(ar[i]);
                *reinterpret_cast<float4*>(&Bs[nbuf][b_row][b_n0 + i * 4]) = CVT4(br[i]);
            }
        }
        __syncthreads();
    }
    #undef CVT4

    // epilogue: stage through smem (reuse As/Bs region), scatter to d_part[ks]
    float* Cs = &As[0][0][0];    // 64 x 68 staging
    #pragma unroll
    for (int i = 0; i < 2; i++)
        #pragma unroll
        for (int j = 0; j < 2; j++)
            wmma::store_matrix_sync(&Cs[(wm + i * 16) * B_STRIDE + wn + j * 16], acc[i][j],
                                    B_STRIDE, wmma::mem_row_major);
    __syncthreads();

    float* pbase = d_part + (size_t)ks * MAXN * HDIM;
    const int c_row  = tid >> 1;              // 0..63
    const int c_col0 = (tid & 1) * 32;
    if (m0 + c_row < M) {
        const int tok = tok_s[c_row];
        float* yptr = pbase + (size_t)tok * H + h0 + c_col0;
        #pragma unroll
        for (int j = 0; j < 32; j += 4)
            *reinterpret_cast<float4*>(yptr + j) =
                *reinterpret_cast<const float4*>(&Cs[c_row * B_STRIDE + c_col0 + j]);
    }
}

// ---------------------------------------------------------------------------
// Kernel 3: reduce partials + bias (fixed order -> deterministic).
// ---------------------------------------------------------------------------
__global__ __launch_bounds__(256) void reduce_kernel(
    const int* __restrict__ idx,
    const float* __restrict__ Bias,   // (NUM_HEADS, H)
    float* __restrict__ Y,            // (N, H)
    int H)
{
    const int i4  = blockIdx.x * 256 + threadIdx.x;       // float4 index
    const int tok = i4 / (H / 4);
    const int c4  = (i4 % (H / 4)) * 4;
    const int head = idx[tok] & (NUM_HEADS - 1);

    const size_t o = (size_t)tok * H + c4;
    float4 s  = *reinterpret_cast<const float4*>(d_part + o);
    #pragma unroll
    for (int k = 1; k < KSPLIT; k++) {
        float4 p = *reinterpret_cast<const float4*>(d_part + (size_t)k * MAXN * HDIM + o);
        s.x += p.x; s.y += p.y; s.z += p.z; s.w += p.w;
    }
    float4 b = *reinterpret_cast<const float4*>(Bias + (size_t)head * H + c4);
    s.x += b.x; s.y += b.y; s.z += b.z; s.w += b.w;
    *reinterpret_cast<float4*>(Y + o) = s;
}

extern "C" void kernel_launch(void* const* d_in, const int* in_sizes, int n_in,
                              void* d_out, int out_size) {
    const float* X    = (const float*)d_in[0];   // (N, D) fp32
    const int*   idx  = (const int*)d_in[1];     // (N,)   int32
    const float* W    = (const float*)d_in[2];   // (16, D, H) fp32
    const float* Bias = (const float*)d_in[3];   // (16, H) fp32
    float*       Y    = (float*)d_out;           // (N, H) fp32

    const int N = in_sizes[1];
    const int D = in_sizes[0] / N;
    const int H = in_sizes[3] / NUM_HEADS;

    bucket16<<<NUM_HEADS, 256>>>(idx, N);

    // grid.y = 4 m-tiles covers buckets up to 256 tokens (11.6 sigma at N=2048)
    dim3 grid(H / TN, 4, NUM_HEADS * KSPLIT);
    mlin_wmma<<<grid, THREADS>>>(X, W, D, H);

    const int total4 = N * H / 4;
    reduce_kernel<<<total4 / 256, 256>>>(idx, Bias, Y, H);
}